// round 2
// baseline (speedup 1.0000x reference)
#include <cuda_runtime.h>
#include <cstdint>

// BezierSurfaceFitter: out[bc,i,j] = sum_{p,q} K[bc,p,q] * bu[i,p] * bv[j,q]
// B*C = 768, H = W = 256, M+1 = N+1 = 32.  bu == bv.
// Separable:  T[p,j] = sum_q K[p,q]*bv[j,q];  out[i,j] = sum_p bu[i,p]*T[p,j]
// fp32 math via packed fma.rn.f32x2 (2 FMA per fma-pipe issue slot).

#define NS  256   // samples per axis
#define NP  32    // degree+1
#define NBC 768   // B*C
#define KT_STRIDE 36   // padded stride for transposed K tile

// Constant separable basis, transposed: g_basisT[p*NS + i] = C(31,p) t_i^p (1-t_i)^(31-p)
__device__ float g_basisT[NP * NS];

__global__ void init_basis_kernel() {
    int i = threadIdx.x;
    if (i >= NS) return;
    double t = ((double)i + 0.5) / (double)NS;
    double u = 1.0 - t;
    double up = 1.0;
#pragma unroll 1
    for (int k = 0; k < NP - 1; ++k) up *= u;   // u^31 (min ~1e-84, fine in fp64)
    double c = 1.0, tp = 1.0;
#pragma unroll 1
    for (int k = 0; k < NP; ++k) {
        g_basisT[k * NS + i] = (float)(c * tp * up);
        c = c * (double)(NP - 1 - k) / (double)(k + 1);
        tp *= t;
        up /= u;
    }
}

__device__ __forceinline__ unsigned long long pack2(float x, float y) {
    unsigned long long r;
    asm("mov.b64 %0, {%1, %2};" : "=l"(r) : "f"(x), "f"(y));
    return r;
}
__device__ __forceinline__ void fma2(unsigned long long& acc,
                                     unsigned long long a, unsigned long long b) {
    asm("fma.rn.f32x2 %0, %1, %2, %0;" : "+l"(acc) : "l"(a), "l"(b));
}
__device__ __forceinline__ float2 unpack2(unsigned long long v) {
    float2 r;
    asm("mov.b64 {%0, %1}, %2;" : "=f"(r.x), "=f"(r.y) : "l"(v));
    return r;
}

// One CTA = one (bc, 128-row i half). 256 threads, 8 warps.
// Static smem only (36.6 KB) -> no cudaFuncSetAttribute needed.
extern "C" __global__ void __launch_bounds__(256)
bezier_fused_kernel(const float* __restrict__ K, float* __restrict__ out) {
    __shared__ float sT[NP * NS];          // [32][256]  T[p][j]
    __shared__ float sKT[NP * KT_STRIDE];  // [32][36]   K transposed: sKT[q][p]

    const int tid  = threadIdx.x;
    const int bx   = blockIdx.x;
    const int bc   = bx >> 1;
    const int half = bx & 1;

    // ---- load this bc's K tile (1024 floats) and transpose into sKT[q][p] ----
    {
        const float4* K4 = (const float4*)(K + (size_t)bc * (NP * NP));
        float4 kv = K4[tid];
        int p  = tid >> 3;
        int q0 = (tid & 7) << 2;
        sKT[(q0 + 0) * KT_STRIDE + p] = kv.x;
        sKT[(q0 + 1) * KT_STRIDE + p] = kv.y;
        sKT[(q0 + 2) * KT_STRIDE + p] = kv.z;
        sKT[(q0 + 3) * KT_STRIDE + p] = kv.w;
    }
    __syncthreads();

    // ---- stage 1: thread j computes T[p][j] for all 32 p (16 f32x2 pairs) ----
    {
        const int j = tid;
        unsigned long long acc[16];
#pragma unroll
        for (int k = 0; k < 16; ++k) acc[k] = 0ull;

#pragma unroll 4
        for (int q = 0; q < NP; ++q) {
            float bvq = __ldg(&g_basisT[q * NS + j]);          // coalesced, L1/L2-hot
            unsigned long long bb = pack2(bvq, bvq);
            const ulonglong2* kr = (const ulonglong2*)(sKT + q * KT_STRIDE);
#pragma unroll
            for (int k2 = 0; k2 < 8; ++k2) {                   // broadcast LDS.128
                ulonglong2 kk = kr[k2];
                fma2(acc[2 * k2 + 0], kk.x, bb);
                fma2(acc[2 * k2 + 1], kk.y, bb);
            }
        }
#pragma unroll
        for (int k = 0; k < 16; ++k) {
            float2 v = unpack2(acc[k]);
            sT[(2 * k + 0) * NS + j] = v.x;
            sT[(2 * k + 1) * NS + j] = v.y;
        }
    }
    __syncthreads();

    // ---- stage 2: out[i,j] = sum_p bu[i,p] * T[p,j]; 8i x 8j per thread ----
    const int w = tid >> 5;
    const int l = tid & 31;
    float* outbase = out + (size_t)bc * (NS * NS);

#pragma unroll 1
    for (int pass = 0; pass < 2; ++pass) {
        const int ibase = half * 128 + pass * 64 + w * 8;

        unsigned long long acc[8][4];
#pragma unroll
        for (int ii = 0; ii < 8; ++ii)
#pragma unroll
            for (int g = 0; g < 4; ++g) acc[ii][g] = 0ull;

#pragma unroll 1
        for (int p = 0; p < NP; ++p) {
            // T fragments: conflict-free LDS.128 across lanes, f32x2-paired
            ulonglong2 ta = *(const ulonglong2*)(sT + p * NS + 4 * l);
            ulonglong2 tb = *(const ulonglong2*)(sT + p * NS + 128 + 4 * l);
            // bu fragments: warp-uniform LDG broadcast from L1-resident table
            float4 bu0 = __ldg((const float4*)(g_basisT + p * NS + ibase));
            float4 bu1 = __ldg((const float4*)(g_basisT + p * NS + ibase + 4));
            float bu_arr[8];
            bu_arr[0] = bu0.x; bu_arr[1] = bu0.y; bu_arr[2] = bu0.z; bu_arr[3] = bu0.w;
            bu_arr[4] = bu1.x; bu_arr[5] = bu1.y; bu_arr[6] = bu1.z; bu_arr[7] = bu1.w;
#pragma unroll
            for (int ii = 0; ii < 8; ++ii) {
                unsigned long long bb = pack2(bu_arr[ii], bu_arr[ii]);
                fma2(acc[ii][0], ta.x, bb);
                fma2(acc[ii][1], ta.y, bb);
                fma2(acc[ii][2], tb.x, bb);
                fma2(acc[ii][3], tb.y, bb);
            }
        }

#pragma unroll
        for (int ii = 0; ii < 8; ++ii) {
            float* o = outbase + (size_t)(ibase + ii) * NS + 4 * l;
            float2 a0 = unpack2(acc[ii][0]);
            float2 a1 = unpack2(acc[ii][1]);
            float2 b0 = unpack2(acc[ii][2]);
            float2 b1 = unpack2(acc[ii][3]);
            *(float4*)(o)       = make_float4(a0.x, a0.y, a1.x, a1.y);
            *(float4*)(o + 128) = make_float4(b0.x, b0.y, b1.x, b1.y);
        }
    }
}

extern "C" void kernel_launch(void* const* d_in, const int* in_sizes, int n_in,
                              void* d_out, int out_size) {
    // Inputs: x (int32, 1 elem, ignored) and K_mat (float32, 768*32*32).
    const float* K = nullptr;
    for (int i = 0; i < n_in; ++i)
        if (in_sizes[i] == NBC * NP * NP) K = (const float*)d_in[i];
    if (!K) K = (const float*)d_in[n_in - 1];

    init_basis_kernel<<<1, NS>>>();
    bezier_fused_kernel<<<NBC * 2, 256>>>(K, (float*)d_out);
}

// round 4
// speedup vs baseline: 1.6003x; 1.6003x over previous
#include <cuda_runtime.h>
#include <cstdint>

// BezierSurfaceFitter: out[bc,i,j] = sum_{p,q} K[bc,p,q] * bu[i,p] * bv[j,q]
// B*C = 768, H = W = 256, M+1 = N+1 = 32.  bu == bv.
// Separable:  T[p,j] = sum_q K[p,q]*bv[j,q];  out[i,j] = sum_p bu[i,p]*T[p,j]
// fp32 math via packed fma.rn.f32x2 (2 FMA per fma-pipe issue slot).
// Basis table computed at COMPILE TIME (constexpr fp64, FTZ below FLT_MIN).

#define NS  256   // samples per axis
#define NP  32    // degree+1
#define NBC 768   // B*C
#define KT_STRIDE 36   // padded stride for transposed K tile

// ---- compile-time Bernstein basis, transposed: v[p*NS+i] = C(31,p) t_i^p (1-t_i)^(31-p)
struct Tbl { float v[NP * NS]; };

// constexpr double->float with flush-to-zero below FLT_MIN (subnormal conversion
// is ill-formed in constant evaluation; contribution is < 1e-37 relative, harmless)
static constexpr float to_f32_ftz(double x) {
    return (x < 1.1754943508222875e-38 && x > -1.1754943508222875e-38)
               ? 0.0f : (float)x;
}

static constexpr Tbl make_tbl() {
    Tbl t{};
    for (int i = 0; i < NS; ++i) {
        double tt = ((double)i + 0.5) / (double)NS;
        double u  = 1.0 - tt;
        double up = 1.0;
        for (int k = 0; k < NP - 1; ++k) up *= u;   // u^31 in fp64
        double c = 1.0, tp = 1.0;
        for (int k = 0; k < NP; ++k) {
            t.v[k * NS + i] = to_f32_ftz(c * tp * up);
            c  = c * (double)(NP - 1 - k) / (double)(k + 1);
            tp *= tt;
            up /= u;
        }
    }
    return t;
}

static constexpr Tbl H_TBL = make_tbl();
__device__ Tbl g_basisG = H_TBL;   // static init, no runtime init kernel

__device__ __forceinline__ unsigned long long pack2(float x, float y) {
    unsigned long long r;
    asm("mov.b64 %0, {%1, %2};" : "=l"(r) : "f"(x), "f"(y));
    return r;
}
__device__ __forceinline__ void fma2(unsigned long long& acc,
                                     unsigned long long a, unsigned long long b) {
    asm("fma.rn.f32x2 %0, %1, %2, %0;" : "+l"(acc) : "l"(a), "l"(b));
}
__device__ __forceinline__ float2 unpack2(unsigned long long v) {
    float2 r;
    asm("mov.b64 {%0, %1}, %2;" : "=f"(r.x), "=f"(r.y) : "l"(v));
    return r;
}

// one stage-2 p-iteration: 32 packed FMAs (64 scalar FMA) on the current fragments
__device__ __forceinline__ void fma_iter(unsigned long long (&acc)[8][4],
                                         const ulonglong2& ta, const ulonglong2& tb,
                                         const float4& b0, const float4& b1) {
    float ba[8] = {b0.x, b0.y, b0.z, b0.w, b1.x, b1.y, b1.z, b1.w};
#pragma unroll
    for (int ii = 0; ii < 8; ++ii) {
        unsigned long long bb = pack2(ba[ii], ba[ii]);
        fma2(acc[ii][0], ta.x, bb);
        fma2(acc[ii][1], ta.y, bb);
        fma2(acc[ii][2], tb.x, bb);
        fma2(acc[ii][3], tb.y, bb);
    }
}

__device__ __forceinline__ void load_frag(const float* sT, int p, int l4, int ibase,
                                          ulonglong2& ta, ulonglong2& tb,
                                          float4& b0, float4& b1) {
    ta = *(const ulonglong2*)(sT + p * NS + l4);            // conflict-free LDS.128
    tb = *(const ulonglong2*)(sT + p * NS + 128 + l4);
    b0 = __ldg((const float4*)(g_basisG.v + p * NS + ibase));     // uniform LDG.128
    b1 = __ldg((const float4*)(g_basisG.v + p * NS + ibase + 4));
}

// One CTA = one (bc, 128-row i half). 256 threads, 8 warps. Static smem only.
extern "C" __global__ void __launch_bounds__(256)
bezier_fused_kernel(const float* __restrict__ K, float* __restrict__ out) {
    __shared__ float sT[NP * NS];          // [32][256]  T[p][j]
    __shared__ float sKT[NP * KT_STRIDE];  // [32][36]   K transposed: sKT[q][p]

    const int tid  = threadIdx.x;
    const int bx   = blockIdx.x;
    const int bc   = bx >> 1;
    const int half = bx & 1;

    // ---- load this bc's K tile (1024 floats), transpose into sKT[q][p] ----
    {
        const float4* K4 = (const float4*)(K + (size_t)bc * (NP * NP));
        float4 kv = K4[tid];
        int p  = tid >> 3;
        int q0 = (tid & 7) << 2;
        sKT[(q0 + 0) * KT_STRIDE + p] = kv.x;
        sKT[(q0 + 1) * KT_STRIDE + p] = kv.y;
        sKT[(q0 + 2) * KT_STRIDE + p] = kv.z;
        sKT[(q0 + 3) * KT_STRIDE + p] = kv.w;
    }
    __syncthreads();

    // ---- stage 1: thread j computes T[p][j] for all 32 p (16 f32x2 pairs) ----
    {
        const int j = tid;
        unsigned long long acc[16];
#pragma unroll
        for (int k = 0; k < 16; ++k) acc[k] = 0ull;

#pragma unroll 4
        for (int q = 0; q < NP; ++q) {
            float bvq = __ldg(&g_basisG.v[q * NS + j]);        // coalesced LDG
            unsigned long long bb = pack2(bvq, bvq);
            const ulonglong2* kr = (const ulonglong2*)(sKT + q * KT_STRIDE);
#pragma unroll
            for (int k2 = 0; k2 < 8; ++k2) {                   // broadcast LDS.128
                ulonglong2 kk = kr[k2];
                fma2(acc[2 * k2 + 0], kk.x, bb);
                fma2(acc[2 * k2 + 1], kk.y, bb);
            }
        }
#pragma unroll
        for (int k = 0; k < 16; ++k) {
            float2 v = unpack2(acc[k]);
            sT[(2 * k + 0) * NS + j] = v.x;
            sT[(2 * k + 1) * NS + j] = v.y;
        }
    }
    __syncthreads();

    // ---- stage 2: out[i,j] = sum_p bu[i,p] * T[p,j]; 8i x 8j per thread ----
    const int w  = tid >> 5;
    const int l4 = (tid & 31) << 2;
    float* outbase = out + (size_t)bc * (NS * NS);

#pragma unroll 1
    for (int pass = 0; pass < 2; ++pass) {
        const int ibase = half * 128 + pass * 64 + w * 8;

        unsigned long long acc[8][4];
#pragma unroll
        for (int ii = 0; ii < 8; ++ii)
#pragma unroll
            for (int g = 0; g < 4; ++g) acc[ii][g] = 0ull;

        // software-pipelined p-loop, double-buffered fragments (constant indices
        // into [2]-arrays -> register renaming, no copy MOVs)
        ulonglong2 ta[2], tb[2];
        float4 b0[2], b1[2];
        load_frag(sT, 0, l4, ibase, ta[0], tb[0], b0[0], b1[0]);

#pragma unroll 1
        for (int p = 0; p < NP; p += 2) {
            int p1 = p + 1;                       // always < 32
            load_frag(sT, p1, l4, ibase, ta[1], tb[1], b0[1], b1[1]);
            fma_iter(acc, ta[0], tb[0], b0[0], b1[0]);
            int p2 = (p + 2 < NP) ? (p + 2) : 0;  // harmless wrap prefetch on last pair
            load_frag(sT, p2, l4, ibase, ta[0], tb[0], b0[0], b1[0]);
            fma_iter(acc, ta[1], tb[1], b0[1], b1[1]);
        }

#pragma unroll
        for (int ii = 0; ii < 8; ++ii) {
            float* o = outbase + (size_t)(ibase + ii) * NS + l4;
            float2 a0 = unpack2(acc[ii][0]);
            float2 a1 = unpack2(acc[ii][1]);
            float2 c0 = unpack2(acc[ii][2]);
            float2 c1 = unpack2(acc[ii][3]);
            *(float4*)(o)       = make_float4(a0.x, a0.y, a1.x, a1.y);
            *(float4*)(o + 128) = make_float4(c0.x, c0.y, c1.x, c1.y);
        }
    }
}

extern "C" void kernel_launch(void* const* d_in, const int* in_sizes, int n_in,
                              void* d_out, int out_size) {
    // Inputs: x (int32, 1 elem, ignored) and K_mat (float32, 768*32*32).
    const float* K = nullptr;
    for (int i = 0; i < n_in; ++i)
        if (in_sizes[i] == NBC * NP * NP) K = (const float*)d_in[i];
    if (!K) K = (const float*)d_in[n_in - 1];

    bezier_fused_kernel<<<NBC * 2, 256>>>(K, (float*)d_out);
}

// round 7
// speedup vs baseline: 2.4997x; 1.5620x over previous
#include <cuda_runtime.h>
#include <cuda_bf16.h>
#include <cstdint>

// BezierSurfaceFitter via mma.sync (HMMA bf16) — tcgen05 unavailable at the
// harness's PTX target (sm_103 without 'a').
// Per bc: out[256,256] = bu[256,32] @ T[32,256];  T[p,j] = sum_q K[p,q]*bv[j,q].
// bf16 H/L split emulates fp32: out ≈ buH·TH + buH·TL + buL·TH  (buL·TL ~2^-18 dropped).
// A (bu) fragments: constexpr bf16 tables in mma A-fragment layout, direct LDG.
// B (T) : stage-1 FFMA2 output written as col-major bf16 rows, ldmatrix.x2 loads.

#define NS  256
#define NP  32
#define NBC 768
#define KT_STRIDE 36
#define BSTRIDE_U32 20   // B row stride: 40 bf16 = 80 bytes = 20 u32

// ---- compile-time Bernstein basis (fp64, flush-to-zero below FLT_MIN) ----
static constexpr float to_f32_ftz(double x) {
    return (x < 1.1754943508222875e-38 && x > -1.1754943508222875e-38)
               ? 0.0f : (float)x;
}
static constexpr uint16_t f32_to_bf16(float f) {
    if (f == 0.0f) return 0;
    uint32_t u = __builtin_bit_cast(uint32_t, f);
    return (uint16_t)((u + 0x7FFFu + ((u >> 16) & 1u)) >> 16);
}
static constexpr float bf16_to_f32(uint16_t h) {
    return __builtin_bit_cast(float, (uint32_t)h << 16);
}
static constexpr double bu_val(int i, int p) {
    double tt = ((double)i + 0.5) / NS, u = 1.0 - tt;
    double c = 1.0;
    for (int k = 0; k < p; ++k) c = c * (double)(NP - 1 - k) / (double)(k + 1);
    double tp = 1.0; for (int k = 0; k < p; ++k) tp *= tt;
    double up = 1.0; for (int k = 0; k < NP - 1 - p; ++k) up *= u;
    return c * tp * up;
}

struct TblP { float v[NP * NS]; };          // p-major fp32 (stage-1 bv)
static constexpr TblP make_p() {
    TblP t{};
    for (int i = 0; i < NS; ++i) {
        double tt = ((double)i + 0.5) / NS, u = 1.0 - tt, up = 1.0;
        for (int k = 0; k < NP - 1; ++k) up *= u;
        double c = 1.0, tp = 1.0;
        for (int k = 0; k < NP; ++k) {
            t.v[k * NS + i] = to_f32_ftz(c * tp * up);
            c = c * (double)(NP - 1 - k) / (double)(k + 1);
            tp *= tt; up /= u;
        }
    }
    return t;
}
// A-side bf16 tables: v[i*16 + cp] = pack(bf16 bu[i][2cp], bf16 bu[i][2cp+1])
struct ATbl { uint32_t v[NS * 16]; };
static constexpr ATbl make_aH() {
    ATbl t{};
    for (int i = 0; i < NS; ++i)
        for (int cp = 0; cp < 16; ++cp) {
            uint16_t h0 = f32_to_bf16(to_f32_ftz(bu_val(i, 2 * cp)));
            uint16_t h1 = f32_to_bf16(to_f32_ftz(bu_val(i, 2 * cp + 1)));
            t.v[i * 16 + cp] = (uint32_t)h0 | ((uint32_t)h1 << 16);
        }
    return t;
}
static constexpr ATbl make_aL() {
    ATbl t{};
    for (int i = 0; i < NS; ++i)
        for (int cp = 0; cp < 16; ++cp) {
            float f0 = to_f32_ftz(bu_val(i, 2 * cp));
            float f1 = to_f32_ftz(bu_val(i, 2 * cp + 1));
            uint16_t l0 = f32_to_bf16(f0 - bf16_to_f32(f32_to_bf16(f0)));
            uint16_t l1 = f32_to_bf16(f1 - bf16_to_f32(f32_to_bf16(f1)));
            t.v[i * 16 + cp] = (uint32_t)l0 | ((uint32_t)l1 << 16);
        }
    return t;
}
static constexpr TblP H_P  = make_p();
static constexpr ATbl H_AH = make_aH();
static constexpr ATbl H_AL = make_aL();
__device__ TblP g_basisP = H_P;
__device__ ATbl g_aH = H_AH;
__device__ ATbl g_aL = H_AL;

// ---- helpers ----
__device__ __forceinline__ uint32_t smem_u32(const void* p) {
    uint32_t a;
    asm("{ .reg .u64 t; cvta.to.shared.u64 t, %1; cvt.u32.u64 %0, t; }" : "=r"(a) : "l"(p));
    return a;
}
__device__ __forceinline__ unsigned long long pack2(float x, float y) {
    unsigned long long r; asm("mov.b64 %0, {%1, %2};" : "=l"(r) : "f"(x), "f"(y)); return r;
}
__device__ __forceinline__ void fma2(unsigned long long& a, unsigned long long b,
                                     unsigned long long c) {
    asm("fma.rn.f32x2 %0, %1, %2, %0;" : "+l"(a) : "l"(b), "l"(c));
}
__device__ __forceinline__ float2 unpack2(unsigned long long v) {
    float2 r; asm("mov.b64 {%0, %1}, %2;" : "=f"(r.x), "=f"(r.y) : "l"(v)); return r;
}
__device__ __forceinline__ void mma16816(float* c, const uint32_t* a, const uint32_t* b) {
    asm volatile("mma.sync.aligned.m16n8k16.row.col.f32.bf16.bf16.f32 "
                 "{%0,%1,%2,%3}, {%4,%5,%6,%7}, {%8,%9}, {%0,%1,%2,%3};"
                 : "+f"(c[0]), "+f"(c[1]), "+f"(c[2]), "+f"(c[3])
                 : "r"(a[0]), "r"(a[1]), "r"(a[2]), "r"(a[3]), "r"(b[0]), "r"(b[1]));
}
__device__ __forceinline__ void ldsm_x2(uint32_t& b0, uint32_t& b1, uint32_t addr) {
    asm volatile("ldmatrix.sync.aligned.m8n8.x2.shared.b16 {%0,%1}, [%2];"
                 : "=r"(b0), "=r"(b1) : "r"(addr));
}

// ---- kernel: one CTA per bc, 256 threads (8 warps) ----
extern "C" __global__ void __launch_bounds__(256, 2)
bezier_hmma_kernel(const float* __restrict__ K, float* __restrict__ out) {
    __shared__ uint32_t sBH[NS * BSTRIDE_U32];   // Tt high: row j, 32 bf16 (+8 pad)
    __shared__ uint32_t sBL[NS * BSTRIDE_U32];   // Tt low
    __shared__ float    sKT[NP * KT_STRIDE];

    const int tid = threadIdx.x;
    const int w   = tid >> 5;
    const int l   = tid & 31;
    const int bc  = blockIdx.x;

    // ---- K tile load + transpose into sKT[q][p] ----
    {
        const float4* K4 = (const float4*)(K + (size_t)bc * (NP * NP));
        float4 kv = K4[tid];
        int p = tid >> 3, q0 = (tid & 7) << 2;
        sKT[(q0 + 0) * KT_STRIDE + p] = kv.x;
        sKT[(q0 + 1) * KT_STRIDE + p] = kv.y;
        sKT[(q0 + 2) * KT_STRIDE + p] = kv.z;
        sKT[(q0 + 3) * KT_STRIDE + p] = kv.w;
    }

    // ---- A fragments from constexpr tables (held in regs for whole kernel) ----
    // mma A frag (m16n8k16 row-major): reg0:(r, c0 pair) reg1:(r+8, c0)
    //                                  reg2:(r, c0+4)    reg3:(r+8, c0+4); ks -> +8 pairs
    uint32_t AH[2][2][4], AL[2][2][4];
    {
        const int r0 = w * 32 + (l >> 2);
        const int c0 = l & 3;
#pragma unroll
        for (int mt = 0; mt < 2; ++mt)
#pragma unroll
            for (int ks = 0; ks < 2; ++ks) {
                int ra = (r0 + 16 * mt) * 16, rb = (r0 + 8 + 16 * mt) * 16;
                int ca = c0 + 8 * ks, cb = c0 + 4 + 8 * ks;
                AH[mt][ks][0] = __ldg(&g_aH.v[ra + ca]);
                AH[mt][ks][1] = __ldg(&g_aH.v[rb + ca]);
                AH[mt][ks][2] = __ldg(&g_aH.v[ra + cb]);
                AH[mt][ks][3] = __ldg(&g_aH.v[rb + cb]);
                AL[mt][ks][0] = __ldg(&g_aL.v[ra + ca]);
                AL[mt][ks][1] = __ldg(&g_aL.v[rb + ca]);
                AL[mt][ks][2] = __ldg(&g_aL.v[ra + cb]);
                AL[mt][ks][3] = __ldg(&g_aL.v[rb + cb]);
            }
    }
    __syncthreads();

    // ---- stage 1: thread j computes T[p][j] for all p; write bf16 H/L rows ----
    {
        const int j = tid;
        unsigned long long acc[16];
#pragma unroll
        for (int k = 0; k < 16; ++k) acc[k] = 0ull;
#pragma unroll 4
        for (int q = 0; q < NP; ++q) {
            float bvq = __ldg(&g_basisP.v[q * NS + j]);
            unsigned long long bb = pack2(bvq, bvq);
            const ulonglong2* kr = (const ulonglong2*)(sKT + q * KT_STRIDE);
#pragma unroll
            for (int k2 = 0; k2 < 8; ++k2) {
                ulonglong2 kk = kr[k2];
                fma2(acc[2 * k2 + 0], kk.x, bb);
                fma2(acc[2 * k2 + 1], kk.y, bb);
            }
        }
#pragma unroll
        for (int k = 0; k < 16; ++k) {
            float2 v = unpack2(acc[k]);                 // T[2k][j], T[2k+1][j]
            __nv_bfloat162 H = __floats2bfloat162_rn(v.x, v.y);
            float lx = v.x - __bfloat162float(H.x);
            float ly = v.y - __bfloat162float(H.y);
            __nv_bfloat162 L = __floats2bfloat162_rn(lx, ly);
            sBH[j * BSTRIDE_U32 + k] = *(uint32_t*)&H;  // row j, k-pair k
            sBL[j * BSTRIDE_U32 + k] = *(uint32_t*)&L;
        }
    }
    __syncthreads();

    // ---- stage 2: HMMA over 8 column chunks of 32 ----
    // ldmatrix lane addressing: lanes 0-7 -> matrix0 rows (k 0-7), 8-15 -> +16B (k 8-15)
    const uint32_t bHbase = smem_u32(sBH) + (uint32_t)(l & 7) * 80u +
                            (uint32_t)((l >> 3) & 1) * 16u;
    const uint32_t bLbase = smem_u32(sBL) + (uint32_t)(l & 7) * 80u +
                            (uint32_t)((l >> 3) & 1) * 16u;
    float* outb = out + ((size_t)bc << 16);

#pragma unroll 1
    for (int jb = 0; jb < 8; ++jb) {
        uint32_t bH[4][2][2], bL[4][2][2];   // [nt][ks][2 regs]
#pragma unroll
        for (int nt = 0; nt < 4; ++nt) {
            uint32_t off = (uint32_t)(jb * 32 + nt * 8) * 80u;
#pragma unroll
            for (int ks = 0; ks < 2; ++ks) {
                ldsm_x2(bH[nt][ks][0], bH[nt][ks][1], bHbase + off + ks * 32u);
                ldsm_x2(bL[nt][ks][0], bL[nt][ks][1], bLbase + off + ks * 32u);
            }
        }

        float c[2][4][4];
#pragma unroll
        for (int mt = 0; mt < 2; ++mt)
#pragma unroll
            for (int nt = 0; nt < 4; ++nt) {
#pragma unroll
                for (int g = 0; g < 4; ++g) c[mt][nt][g] = 0.0f;
                mma16816(c[mt][nt], AH[mt][0], bH[nt][0]);
                mma16816(c[mt][nt], AH[mt][1], bH[nt][1]);
                mma16816(c[mt][nt], AH[mt][0], bL[nt][0]);
                mma16816(c[mt][nt], AH[mt][1], bL[nt][1]);
                mma16816(c[mt][nt], AL[mt][0], bH[nt][0]);
                mma16816(c[mt][nt], AL[mt][1], bH[nt][1]);
            }

#pragma unroll
        for (int mt = 0; mt < 2; ++mt)
#pragma unroll
            for (int nt = 0; nt < 4; ++nt) {
                int row = w * 32 + mt * 16 + (l >> 2);
                int col = jb * 32 + nt * 8 + 2 * (l & 3);
                *(float2*)(outb + (size_t)row * NS + col) =
                    make_float2(c[mt][nt][0], c[mt][nt][1]);
                *(float2*)(outb + (size_t)(row + 8) * NS + col) =
                    make_float2(c[mt][nt][2], c[mt][nt][3]);
            }
    }
}

extern "C" void kernel_launch(void* const* d_in, const int* in_sizes, int n_in,
                              void* d_out, int out_size) {
    const float* K = nullptr;
    for (int i = 0; i < n_in; ++i)
        if (in_sizes[i] == NBC * NP * NP) K = (const float*)d_in[i];
    if (!K) K = (const float*)d_in[n_in - 1];

    bezier_hmma_kernel<<<NBC, 256>>>(K, (float*)d_out);
}

// round 8
// speedup vs baseline: 2.5271x; 1.0109x over previous
#include <cuda_runtime.h>
#include <cuda_bf16.h>
#include <cstdint>

// BezierSurfaceFitter via mma.sync (HMMA bf16), occupancy-3 layout.
// CTA = (bc, j-half): grid 1536. Per bc: out[256,256] = bu[256,32] @ T[32,256].
// bf16 H/L split: out ≈ buH·TH + buH·TL + buL·TH  (buL·TL ~2^-18 dropped).

#define NS  256
#define NP  32
#define NBC 768
#define KT_STRIDE 36
#define BSTRIDE_U32 20   // B row stride: 40 bf16 = 80 bytes
#define JH  128          // j columns per CTA (half)

// ---- compile-time Bernstein basis (fp64, flush-to-zero below FLT_MIN) ----
static constexpr float to_f32_ftz(double x) {
    return (x < 1.1754943508222875e-38 && x > -1.1754943508222875e-38)
               ? 0.0f : (float)x;
}
static constexpr uint16_t f32_to_bf16(float f) {
    if (f == 0.0f) return 0;
    uint32_t u = __builtin_bit_cast(uint32_t, f);
    return (uint16_t)((u + 0x7FFFu + ((u >> 16) & 1u)) >> 16);
}
static constexpr float bf16_to_f32(uint16_t h) {
    return __builtin_bit_cast(float, (uint32_t)h << 16);
}
static constexpr double bu_val(int i, int p) {
    double tt = ((double)i + 0.5) / NS, u = 1.0 - tt;
    double c = 1.0;
    for (int k = 0; k < p; ++k) c = c * (double)(NP - 1 - k) / (double)(k + 1);
    double tp = 1.0; for (int k = 0; k < p; ++k) tp *= tt;
    double up = 1.0; for (int k = 0; k < NP - 1 - p; ++k) up *= u;
    return c * tp * up;
}
struct TblP { float v[NP * NS]; };          // p-major fp32 (stage-1 bv)
static constexpr TblP make_p() {
    TblP t{};
    for (int i = 0; i < NS; ++i)
        for (int k = 0; k < NP; ++k)
            t.v[k * NS + i] = to_f32_ftz(bu_val(i, k));
    return t;
}
// A-side bf16 tables: v[i*16 + cp] = pack(bf16 bu[i][2cp], bf16 bu[i][2cp+1])
struct ATbl { uint32_t v[NS * 16]; };
static constexpr ATbl make_aH() {
    ATbl t{};
    for (int i = 0; i < NS; ++i)
        for (int cp = 0; cp < 16; ++cp) {
            uint16_t h0 = f32_to_bf16(to_f32_ftz(bu_val(i, 2 * cp)));
            uint16_t h1 = f32_to_bf16(to_f32_ftz(bu_val(i, 2 * cp + 1)));
            t.v[i * 16 + cp] = (uint32_t)h0 | ((uint32_t)h1 << 16);
        }
    return t;
}
static constexpr ATbl make_aL() {
    ATbl t{};
    for (int i = 0; i < NS; ++i)
        for (int cp = 0; cp < 16; ++cp) {
            float f0 = to_f32_ftz(bu_val(i, 2 * cp));
            float f1 = to_f32_ftz(bu_val(i, 2 * cp + 1));
            uint16_t l0 = f32_to_bf16(f0 - bf16_to_f32(f32_to_bf16(f0)));
            uint16_t l1 = f32_to_bf16(f1 - bf16_to_f32(f32_to_bf16(f1)));
            t.v[i * 16 + cp] = (uint32_t)l0 | ((uint32_t)l1 << 16);
        }
    return t;
}
static constexpr TblP H_P  = make_p();
static constexpr ATbl H_AH = make_aH();
static constexpr ATbl H_AL = make_aL();
__device__ TblP g_basisP = H_P;
__device__ ATbl g_aH = H_AH;
__device__ ATbl g_aL = H_AL;

// ---- helpers ----
__device__ __forceinline__ uint32_t smem_u32(const void* p) {
    uint32_t a;
    asm("{ .reg .u64 t; cvta.to.shared.u64 t, %1; cvt.u32.u64 %0, t; }" : "=r"(a) : "l"(p));
    return a;
}
__device__ __forceinline__ unsigned long long pack2(float x, float y) {
    unsigned long long r; asm("mov.b64 %0, {%1, %2};" : "=l"(r) : "f"(x), "f"(y)); return r;
}
__device__ __forceinline__ void fma2(unsigned long long& a, unsigned long long b,
                                     unsigned long long c) {
    asm("fma.rn.f32x2 %0, %1, %2, %0;" : "+l"(a) : "l"(b), "l"(c));
}
__device__ __forceinline__ float2 unpack2(unsigned long long v) {
    float2 r; asm("mov.b64 {%0, %1}, %2;" : "=f"(r.x), "=f"(r.y) : "l"(v)); return r;
}
__device__ __forceinline__ void mma16816(float* c, const uint32_t* a, const uint32_t* b) {
    asm volatile("mma.sync.aligned.m16n8k16.row.col.f32.bf16.bf16.f32 "
                 "{%0,%1,%2,%3}, {%4,%5,%6,%7}, {%8,%9}, {%0,%1,%2,%3};"
                 : "+f"(c[0]), "+f"(c[1]), "+f"(c[2]), "+f"(c[3])
                 : "r"(a[0]), "r"(a[1]), "r"(a[2]), "r"(a[3]), "r"(b[0]), "r"(b[1]));
}
// x4: one call loads both k-halves of both ksteps (same 8 j-rows).
// lanes 0-7: +0 (k0-7), 8-15: +16B (k8-15), 16-23: +32B (k16-23), 24-31: +48B (k24-31)
__device__ __forceinline__ void ldsm_x4(uint32_t* b, uint32_t addr) {
    asm volatile("ldmatrix.sync.aligned.m8n8.x4.shared.b16 {%0,%1,%2,%3}, [%4];"
                 : "=r"(b[0]), "=r"(b[1]), "=r"(b[2]), "=r"(b[3]) : "r"(addr));
}

// ---- kernel: CTA = (bc, j-half), 256 threads (8 warps), 3 CTAs/SM ----
extern "C" __global__ void __launch_bounds__(256, 3)
bezier_hmma_kernel(const float* __restrict__ K, float* __restrict__ out) {
    __shared__ uint32_t sBH[JH * BSTRIDE_U32];   // Tt-half high: row j, 32 bf16 (+pad)
    __shared__ uint32_t sBL[JH * BSTRIDE_U32];   // Tt-half low
    __shared__ float    sKT[NP * KT_STRIDE];

    const int tid  = threadIdx.x;
    const int w    = tid >> 5;
    const int l    = tid & 31;
    const int bc   = blockIdx.x >> 1;
    const int half = blockIdx.x & 1;

    // ---- K tile load + transpose into sKT[q][p] ----
    {
        const float4* K4 = (const float4*)(K + (size_t)bc * (NP * NP));
        float4 kv = K4[tid];
        int p = tid >> 3, q0 = (tid & 7) << 2;
        sKT[(q0 + 0) * KT_STRIDE + p] = kv.x;
        sKT[(q0 + 1) * KT_STRIDE + p] = kv.y;
        sKT[(q0 + 2) * KT_STRIDE + p] = kv.z;
        sKT[(q0 + 3) * KT_STRIDE + p] = kv.w;
    }

    // ---- A fragments (resident in regs): rows w*32..+31, all 32 p ----
    uint32_t AH[2][2][4], AL[2][2][4];
    {
        const int r0 = w * 32 + (l >> 2);
        const int c0 = l & 3;
#pragma unroll
        for (int mt = 0; mt < 2; ++mt)
#pragma unroll
            for (int ks = 0; ks < 2; ++ks) {
                int ra = (r0 + 16 * mt) * 16, rb = (r0 + 8 + 16 * mt) * 16;
                int ca = c0 + 8 * ks, cb = c0 + 4 + 8 * ks;
                AH[mt][ks][0] = __ldg(&g_aH.v[ra + ca]);
                AH[mt][ks][1] = __ldg(&g_aH.v[rb + ca]);
                AH[mt][ks][2] = __ldg(&g_aH.v[ra + cb]);
                AH[mt][ks][3] = __ldg(&g_aH.v[rb + cb]);
                AL[mt][ks][0] = __ldg(&g_aL.v[ra + ca]);
                AL[mt][ks][1] = __ldg(&g_aL.v[rb + ca]);
                AL[mt][ks][2] = __ldg(&g_aL.v[ra + cb]);
                AL[mt][ks][3] = __ldg(&g_aL.v[rb + cb]);
            }
    }
    __syncthreads();

    // ---- stage 1: thread = (j in 0..127, p-half); 16 p's per thread ----
    {
        const int j  = tid & 127;
        const int ph = tid >> 7;                  // 0: p 0-15, 1: p 16-31
        unsigned long long acc[8];
#pragma unroll
        for (int k = 0; k < 8; ++k) acc[k] = 0ull;
#pragma unroll 4
        for (int q = 0; q < NP; ++q) {
            float bvq = __ldg(&g_basisP.v[q * NS + half * JH + j]);
            unsigned long long bb = pack2(bvq, bvq);
            const ulonglong2* kr =
                (const ulonglong2*)(sKT + q * KT_STRIDE + ph * 16);
#pragma unroll
            for (int k2 = 0; k2 < 4; ++k2) {      // 4x LDS.128 broadcast
                ulonglong2 kk = kr[k2];
                fma2(acc[2 * k2 + 0], kk.x, bb);
                fma2(acc[2 * k2 + 1], kk.y, bb);
            }
        }
#pragma unroll
        for (int k = 0; k < 8; ++k) {
            float2 v = unpack2(acc[k]);           // T[ph*16+2k][j], T[..+1][j]
            __nv_bfloat162 H = __floats2bfloat162_rn(v.x, v.y);
            float lx = v.x - __bfloat162float(H.x);
            float ly = v.y - __bfloat162float(H.y);
            __nv_bfloat162 L = __floats2bfloat162_rn(lx, ly);
            sBH[j * BSTRIDE_U32 + ph * 8 + k] = *(uint32_t*)&H;
            sBL[j * BSTRIDE_U32 + ph * 8 + k] = *(uint32_t*)&L;
        }
    }
    __syncthreads();

    // ---- stage 2: HMMA over 8 chunks of 16 local cols ----
    const uint32_t lane_off = (uint32_t)(l & 7) * 80u + (uint32_t)(l >> 3) * 16u;
    const uint32_t bHbase = smem_u32(sBH) + lane_off;
    const uint32_t bLbase = smem_u32(sBL) + lane_off;
    float* outb = out + ((size_t)bc << 16) + half * JH;

#pragma unroll 1
    for (int jb = 0; jb < 8; ++jb) {
        uint32_t bH[2][4], bL[2][4];              // [nt][ks*2+reg]
#pragma unroll
        for (int nt = 0; nt < 2; ++nt) {
            uint32_t off = (uint32_t)(jb * 16 + nt * 8) * 80u;
            ldsm_x4(bH[nt], bHbase + off);
            ldsm_x4(bL[nt], bLbase + off);
        }

        float c[2][2][4];
#pragma unroll
        for (int mt = 0; mt < 2; ++mt)
#pragma unroll
            for (int nt = 0; nt < 2; ++nt) {
#pragma unroll
                for (int g = 0; g < 4; ++g) c[mt][nt][g] = 0.0f;
                mma16816(c[mt][nt], AH[mt][0], &bH[nt][0]);
                mma16816(c[mt][nt], AH[mt][1], &bH[nt][2]);
                mma16816(c[mt][nt], AH[mt][0], &bL[nt][0]);
                mma16816(c[mt][nt], AH[mt][1], &bL[nt][2]);
                mma16816(c[mt][nt], AL[mt][0], &bH[nt][0]);
                mma16816(c[mt][nt], AL[mt][1], &bH[nt][2]);
            }

#pragma unroll
        for (int mt = 0; mt < 2; ++mt)
#pragma unroll
            for (int nt = 0; nt < 2; ++nt) {
                int row = w * 32 + mt * 16 + (l >> 2);
                int col = jb * 16 + nt * 8 + 2 * (l & 3);
                *(float2*)(outb + (size_t)row * NS + col) =
                    make_float2(c[mt][nt][0], c[mt][nt][1]);
                *(float2*)(outb + (size_t)(row + 8) * NS + col) =
                    make_float2(c[mt][nt][2], c[mt][nt][3]);
            }
    }
}

extern "C" void kernel_launch(void* const* d_in, const int* in_sizes, int n_in,
                              void* d_out, int out_size) {
    const float* K = nullptr;
    for (int i = 0; i < n_in; ++i)
        if (in_sizes[i] == NBC * NP * NP) K = (const float*)d_in[i];
    if (!K) K = (const float*)d_in[n_in - 1];

    bezier_hmma_kernel<<<NBC * 2, 256>>>(K, (float*)d_out);
}